// round 14
// baseline (speedup 1.0000x reference)
#include <cuda_runtime.h>
#include <math.h>
#include <stdint.h>

#define N_NODES 100000
#define NE      1600000
#define H1H     8
#define C1C     16
#define D1      128
#define NC      40
#define NEG     0.2f

// Scratch: __device__ globals referenced ONLY inside device code (GB300 ATS
// trap: passing the symbol as a kernel arg from host passes the host shadow).
__device__ __align__(256) float g_h1[N_NODES * D1];
__device__ __align__(256) float g_hrelu[N_NODES * D1];
__device__ __align__(256) float g_h2[N_NODES * NC];
__device__ __align__(256) float g_ssrc1[N_NODES * H1H];
__device__ __align__(256) float g_sdst1[N_NODES * H1H];
__device__ __align__(256) float g_ssrc2[N_NODES];
__device__ __align__(256) float g_sdst2[N_NODES];
__device__ __align__(256) int   g_deg[N_NODES];
__device__ __align__(256) int   g_cur[N_NODES];
__device__ __align__(256) int   g_off[N_NODES + 1];
__device__ __align__(256) int   g_srt[NE];

#define SCAN_B 1024
#define NSB ((N_NODES + SCAN_B - 1) / SCAN_B)   /* 98 */
__device__ __align__(256) int g_part[NSB];

__device__ __forceinline__ float lrelu(float x) { return x > 0.f ? x : NEG * x; }

__device__ __forceinline__ uint32_t f2tf32(float v) {
    uint32_t r;
    asm("cvt.rna.tf32.f32 %0, %1;" : "=r"(r) : "f"(v));
    return r;
}

__device__ __forceinline__ void mma_tf32(float* c, const uint32_t* a, uint32_t b0, uint32_t b1) {
    asm volatile(
        "mma.sync.aligned.m16n8k8.row.col.f32.tf32.tf32.f32 "
        "{%0,%1,%2,%3}, {%4,%5,%6,%7}, {%8,%9}, {%0,%1,%2,%3};"
        : "+f"(c[0]), "+f"(c[1]), "+f"(c[2]), "+f"(c[3])
        : "r"(a[0]), "r"(a[1]), "r"(a[2]), "r"(a[3]), "r"(b0), "r"(b1));
}

// ---- CSR build (edge_index: int32 planar) ----
__global__ void k_zero() {
    int i = blockIdx.x * blockDim.x + threadIdx.x;
    if (i < N_NODES) { g_deg[i] = 0; g_cur[i] = 0; }
}
__global__ void k_hist(const int* __restrict__ ei) {
    int e = blockIdx.x * blockDim.x + threadIdx.x;
    if (e < NE) atomicAdd(&g_deg[ei[NE + e]], 1);
}
__global__ void k_scan1() {
    __shared__ int s[SCAN_B];
    int t = threadIdx.x, i = blockIdx.x * SCAN_B + t;
    int v = (i < N_NODES) ? g_deg[i] : 0;
    s[t] = v; __syncthreads();
    for (int d = 1; d < SCAN_B; d <<= 1) {
        int x = (t >= d) ? s[t - d] : 0; __syncthreads();
        s[t] += x; __syncthreads();
    }
    if (i < N_NODES) g_off[i] = s[t] - v;
    if (t == SCAN_B - 1) g_part[blockIdx.x] = s[t];
}
__global__ void k_scan2() {
    __shared__ int s[128];
    int t = threadIdx.x;
    int v = (t < NSB) ? g_part[t] : 0;
    s[t] = v; __syncthreads();
    for (int d = 1; d < 128; d <<= 1) {
        int x = (t >= d) ? s[t - d] : 0; __syncthreads();
        s[t] += x; __syncthreads();
    }
    if (t < NSB) g_part[t] = s[t] - v;
}
__global__ void k_scan3() {
    int i = blockIdx.x * blockDim.x + threadIdx.x;
    if (i < N_NODES) g_off[i] += g_part[i >> 10];
    if (i == 0) g_off[N_NODES] = NE;
}
__global__ void k_scatter(const int* __restrict__ ei) {
    int e = blockIdx.x * blockDim.x + threadIdx.x;
    if (e < NE) {
        int d = ei[NE + e];
        int pos = g_off[d] + atomicAdd(&g_cur[d], 1);
        g_srt[pos] = ei[e];
    }
}

// ---- GEMM1 via tf32 tensor cores (3xTF32 compensation): g_h1 = x @ W1 ----
// Block tile 128x128, 8 warps in 4(M) x 2(N); warp tile 32x64; K chunk 16.
__global__ void k_gemm1t(const float* __restrict__ A, const float* __restrict__ B) {
    __shared__ uint32_t As_hi[16][133], As_lo[16][133];
    __shared__ uint32_t Bs_hi[16][132], Bs_lo[16][132];
    int tid = threadIdx.x;
    int lane = tid & 31, warp = tid >> 5;
    int warpM = warp >> 1, warpN = warp & 1;   // 4 x 2
    int row0 = blockIdx.x * 128;
    int q4 = lane >> 2, r4 = lane & 3;

    float c[2][8][4];
#pragma unroll
    for (int mi = 0; mi < 2; mi++)
#pragma unroll
        for (int ni = 0; ni < 8; ni++)
#pragma unroll
            for (int k = 0; k < 4; k++) c[mi][ni][k] = 0.f;

    for (int kb = 0; kb < 128; kb += 16) {
        // A tile 128 rows x 16 cols: 512 float4, 2 per thread, store transposed
#pragma unroll
        for (int q = 0; q < 2; q++) {
            int f = tid + 256 * q;
            int r = f >> 2, c4 = f & 3;
            int row = row0 + r;
            float4 v = (row < N_NODES)
                       ? *(const float4*)&A[row * 128 + kb + c4 * 4]
                       : make_float4(0.f, 0.f, 0.f, 0.f);
            float vv[4] = {v.x, v.y, v.z, v.w};
#pragma unroll
            for (int j = 0; j < 4; j++) {
                uint32_t hb = f2tf32(vv[j]);
                float hf = __uint_as_float(hb);
                As_hi[c4 * 4 + j][r] = hb;
                As_lo[c4 * 4 + j][r] = f2tf32(vv[j] - hf);
            }
        }
        // B tile 16 rows x 128 cols: 512 float4, 2 per thread
#pragma unroll
        for (int q = 0; q < 2; q++) {
            int f = tid + 256 * q;
            int kk = f >> 5, c4 = f & 31;
            float4 v = *(const float4*)&B[(kb + kk) * 128 + c4 * 4];
            float vv[4] = {v.x, v.y, v.z, v.w};
            uint32_t hb[4], lb[4];
#pragma unroll
            for (int j = 0; j < 4; j++) {
                hb[j] = f2tf32(vv[j]);
                lb[j] = f2tf32(vv[j] - __uint_as_float(hb[j]));
            }
            *(uint4*)&Bs_hi[kk][c4 * 4] = make_uint4(hb[0], hb[1], hb[2], hb[3]);
            *(uint4*)&Bs_lo[kk][c4 * 4] = make_uint4(lb[0], lb[1], lb[2], lb[3]);
        }
        __syncthreads();

#pragma unroll
        for (int ks = 0; ks < 16; ks += 8) {
            uint32_t ah[2][4], al[2][4];
#pragma unroll
            for (int mi = 0; mi < 2; mi++) {
                int r = warpM * 32 + mi * 16 + q4;
                int cc = ks + r4;
                ah[mi][0] = As_hi[cc][r];     ah[mi][1] = As_hi[cc][r + 8];
                ah[mi][2] = As_hi[cc + 4][r]; ah[mi][3] = As_hi[cc + 4][r + 8];
                al[mi][0] = As_lo[cc][r];     al[mi][1] = As_lo[cc][r + 8];
                al[mi][2] = As_lo[cc + 4][r]; al[mi][3] = As_lo[cc + 4][r + 8];
            }
#pragma unroll
            for (int ni = 0; ni < 8; ni++) {
                int cN = warpN * 64 + ni * 8 + q4;
                int kB = ks + r4;
                uint32_t bh0 = Bs_hi[kB][cN], bh1 = Bs_hi[kB + 4][cN];
                uint32_t bl0 = Bs_lo[kB][cN], bl1 = Bs_lo[kB + 4][cN];
#pragma unroll
                for (int mi = 0; mi < 2; mi++) {
                    mma_tf32(c[mi][ni], ah[mi], bh0, bh1);
                    mma_tf32(c[mi][ni], ah[mi], bl0, bl1);
                    mma_tf32(c[mi][ni], al[mi], bh0, bh1);
                }
            }
        }
        __syncthreads();
    }

    // epilogue: fragment c0,c1 -> (row, 2*(lane&3)), c2,c3 -> row+8
#pragma unroll
    for (int mi = 0; mi < 2; mi++) {
        int rA = row0 + warpM * 32 + mi * 16 + q4;
        int rB = rA + 8;
#pragma unroll
        for (int ni = 0; ni < 8; ni++) {
            int col = warpN * 64 + ni * 8 + 2 * r4;
            if (rA < N_NODES)
                *(float2*)&g_h1[rA * 128 + col] = make_float2(c[mi][ni][0], c[mi][ni][1]);
            if (rB < N_NODES)
                *(float2*)&g_h1[rB * 128 + col] = make_float2(c[mi][ni][2], c[mi][ni][3]);
        }
    }
}

// ---- s1 logits (standalone) ----
__global__ void k_s1(const float* __restrict__ a_src, const float* __restrict__ a_dst) {
    int i = blockIdx.x * blockDim.x + threadIdx.x;
    if (i >= N_NODES * H1H) return;
    int n = i >> 3, h = i & 7;
    const float* hp = &g_h1[n * D1 + h * C1C];
    float ss = 0.f, sd = 0.f;
#pragma unroll
    for (int c = 0; c < C1C; c++) {
        float v = hp[c];
        ss += v * a_src[h * C1C + c];
        sd += v * a_dst[h * C1C + c];
    }
    g_ssrc1[i] = ss; g_sdst1[i] = sd;
}

// ---- GEMM2 + fused s2 logits ----
__global__ void k_gemm2s(const float* __restrict__ B,
                         const float* __restrict__ as2, const float* __restrict__ ad2) {
    __shared__ float As[16][132];
    __shared__ float Bs[16][48];
    int tid = threadIdx.x, tx = tid & 15, ty = tid >> 4;
    int row0 = blockIdx.x * 128, r0 = ty * 8;
    float acc[8][3];
#pragma unroll
    for (int i = 0; i < 8; i++)
#pragma unroll
        for (int j = 0; j < 3; j++) acc[i][j] = 0.f;
    for (int kb = 0; kb < 128; kb += 16) {
        for (int l = tid; l < 2048; l += 256) {
            int r = l >> 4, kk = l & 15, row = row0 + r;
            As[kk][r] = (row < N_NODES) ? g_hrelu[row * 128 + kb + kk] : 0.f;
        }
        for (int l = tid; l < 640; l += 256) {
            int kk = l / 40, col = l % 40;
            Bs[kk][col] = B[(kb + kk) * 40 + col];
        }
        __syncthreads();
#pragma unroll
        for (int kk = 0; kk < 16; kk++) {
            float a[8];
#pragma unroll
            for (int i = 0; i < 8; i++) a[i] = As[kk][r0 + i];
            float b0 = Bs[kk][tx], b1 = Bs[kk][tx + 16], b2 = (tx < 8) ? Bs[kk][tx + 32] : 0.f;
#pragma unroll
            for (int i = 0; i < 8; i++) {
                acc[i][0] += a[i] * b0; acc[i][1] += a[i] * b1; acc[i][2] += a[i] * b2;
            }
        }
        __syncthreads();
    }
    float a0 = as2[tx], a1 = as2[tx + 16], a2 = (tx < 8) ? as2[tx + 32] : 0.f;
    float d0 = ad2[tx], d1 = ad2[tx + 16], d2 = (tx < 8) ? ad2[tx + 32] : 0.f;
#pragma unroll
    for (int i = 0; i < 8; i++) {
        int row = row0 + r0 + i;
        if (row >= N_NODES) continue;
        g_h2[row * 40 + tx] = acc[i][0];
        g_h2[row * 40 + tx + 16] = acc[i][1];
        if (tx < 8) g_h2[row * 40 + tx + 32] = acc[i][2];
        float ps = acc[i][0] * a0 + acc[i][1] * a1 + acc[i][2] * a2;
        float pd = acc[i][0] * d0 + acc[i][1] * d1 + acc[i][2] * d2;
#pragma unroll
        for (int o = 8; o; o >>= 1) {
            ps += __shfl_xor_sync(0xffffffffu, ps, o);
            pd += __shfl_xor_sync(0xffffffffu, pd, o);
        }
        if (tx == 0) { g_ssrc2[row] = ps; g_sdst2[row] = pd; }
    }
}

// ---- layer1 aggregation: warp/node, single-pass online softmax ----
__global__ void k_agg1(const float* __restrict__ b1) {
    int warp = (blockIdx.x * blockDim.x + threadIdx.x) >> 5;
    int lane = threadIdx.x & 31;
    if (warp >= N_NODES) return;
    int i = warp, h = lane >> 2;
    float sdst = g_sdst1[i * H1H + h];
    float m = lrelu(g_ssrc1[i * H1H + h] + sdst);
    int beg = g_off[i], end = g_off[i + 1];
    const float4* hp = (const float4*)g_h1;
    float den = 1.f;
    float4 acc = hp[i * 32 + lane];
    int s = (beg < end) ? g_srt[beg] : 0;
    for (int j = beg; j < end; j++) {
        int snext = (j + 1 < end) ? g_srt[j + 1] : 0;
        float e = lrelu(g_ssrc1[s * H1H + h] + sdst);
        float p;
        if (e > m) {
            float sc = __expf(m - e);
            den *= sc;
            acc.x *= sc; acc.y *= sc; acc.z *= sc; acc.w *= sc;
            m = e; p = 1.f;
        } else {
            p = __expf(e - m);
        }
        float4 w = hp[s * 32 + lane];
        den += p;
        acc.x += p * w.x; acc.y += p * w.y; acc.z += p * w.z; acc.w += p * w.w;
        s = snext;
    }
    float inv = 1.f / den;
    float4 o;
    o.x = fmaxf(acc.x * inv + b1[lane * 4 + 0], 0.f);
    o.y = fmaxf(acc.y * inv + b1[lane * 4 + 1], 0.f);
    o.z = fmaxf(acc.z * inv + b1[lane * 4 + 2], 0.f);
    o.w = fmaxf(acc.w * inv + b1[lane * 4 + 3], 0.f);
    ((float4*)g_hrelu)[i * 32 + lane] = o;
}

// ---- layer2 aggregation (online softmax) + log_softmax ----
__global__ void k_agg2(const float* __restrict__ b2, float* __restrict__ out) {
    int warp = (blockIdx.x * blockDim.x + threadIdx.x) >> 5;
    int lane = threadIdx.x & 31;
    if (warp >= N_NODES) return;
    int i = warp;
    float sdst = g_sdst2[i];
    float m = lrelu(g_ssrc2[i] + sdst);
    int beg = g_off[i], end = g_off[i + 1];
    float den = 1.f;
    float a0 = g_h2[i * NC + lane];
    float a1 = (lane < 8) ? g_h2[i * NC + 32 + lane] : 0.f;
    int s = (beg < end) ? g_srt[beg] : 0;
    for (int j = beg; j < end; j++) {
        int snext = (j + 1 < end) ? g_srt[j + 1] : 0;
        float e = lrelu(g_ssrc2[s] + sdst);
        float p;
        if (e > m) {
            float sc = __expf(m - e);
            den *= sc; a0 *= sc; a1 *= sc;
            m = e; p = 1.f;
        } else {
            p = __expf(e - m);
        }
        den += p;
        a0 += p * g_h2[s * NC + lane];
        if (lane < 8) a1 += p * g_h2[s * NC + 32 + lane];
        s = snext;
    }
    float inv = 1.f / den;
    float v0 = a0 * inv + b2[lane];
    float v1 = (lane < 8) ? (a1 * inv + b2[32 + lane]) : -INFINITY;
    float mm = fmaxf(v0, v1);
#pragma unroll
    for (int d = 16; d; d >>= 1) mm = fmaxf(mm, __shfl_xor_sync(0xffffffffu, mm, d));
    float se = __expf(v0 - mm) + ((lane < 8) ? __expf(v1 - mm) : 0.f);
#pragma unroll
    for (int d = 16; d; d >>= 1) se += __shfl_xor_sync(0xffffffffu, se, d);
    float ls = mm + logf(se);
    out[i * NC + lane] = v0 - ls;
    if (lane < 8) out[i * NC + 32 + lane] = v1 - ls;
}

// ---- launch ----
extern "C" void kernel_launch(void* const* d_in, const int* in_sizes, int n_in,
                              void* d_out, int out_size) {
    const float* x   = (const float*)d_in[0];
    const int*   ei  = (const int*)d_in[1];
    const float* W1  = (const float*)d_in[2];
    const float* as1 = (const float*)d_in[3];
    const float* ad1 = (const float*)d_in[4];
    const float* b1  = (const float*)d_in[5];
    const float* W2  = (const float*)d_in[6];
    const float* as2 = (const float*)d_in[7];
    const float* ad2 = (const float*)d_in[8];
    const float* b2  = (const float*)d_in[9];
    float* out = (float*)d_out;

    k_zero<<<(N_NODES + 255) / 256, 256>>>();
    k_hist<<<(NE + 255) / 256, 256>>>(ei);
    k_scan1<<<NSB, SCAN_B>>>();
    k_scan2<<<1, 128>>>();
    k_scan3<<<(N_NODES + 1023) / 1024, 1024>>>();
    k_scatter<<<(NE + 255) / 256, 256>>>(ei);

    k_gemm1t<<<(N_NODES + 127) / 128, 256>>>(x, W1);
    k_s1<<<(N_NODES * H1H + 255) / 256, 256>>>(as1, ad1);
    k_agg1<<<(N_NODES * 32 + 255) / 256, 256>>>(b1);

    k_gemm2s<<<(N_NODES + 127) / 128, 256>>>(W2, as2, ad2);
    k_agg2<<<(N_NODES * 32 + 255) / 256, 256>>>(b2, out);
}